// round 1
// baseline (speedup 1.0000x reference)
#include <cuda_runtime.h>

#define NN 20000
#define EE 320000
#define HF 256          // heads * out_f
#define NEG 0.2f

// ---------------- scratch (static device globals; no allocation) ----------------
__device__ float g_val [NN * HF];
__device__ float g_hsrc[NN * HF];
__device__ float g_hdst[NN * HF];
__device__ int   g_deg[NN];
__device__ int   g_rowptr[NN + 1];
__device__ int   g_cursor[NN];
__device__ int   g_srcs[EE];
__device__ int   g_bsum[32];
__device__ int   g_boff[32];

// ---------------- f32x2 helpers (sm_100+ packed fp32 pipe) ----------------
__device__ __forceinline__ unsigned long long pk2(float lo, float hi) {
    unsigned long long r;
    asm("mov.b64 %0, {%1, %2};" : "=l"(r)
        : "r"(__float_as_uint(lo)), "r"(__float_as_uint(hi)));
    return r;
}
__device__ __forceinline__ void fma2(unsigned long long& d,
                                     unsigned long long a, unsigned long long b) {
    asm("fma.rn.f32x2 %0, %1, %2, %0;" : "+l"(d) : "l"(a), "l"(b));
}
__device__ __forceinline__ float lo32(unsigned long long v) { return __uint_as_float((unsigned)v); }
__device__ __forceinline__ float hi32(unsigned long long v) { return __uint_as_float((unsigned)(v >> 32)); }

// ---------------- fused 3-way projection GEMM ----------------
// C[20000,768] = x[20000,128] @ [W;W1;W2]^T, written to g_val/g_hsrc/g_hdst.
// Tile 128x64, k-slab 32, 256 threads, 8x4 micro-tile via f32x2 row pairs.
__global__ __launch_bounds__(256) void gemm_kernel(
    const float* __restrict__ x,
    const float* __restrict__ W,  const float* __restrict__ W1,
    const float* __restrict__ W2)
{
    __shared__ float As[128 * 32];   // [row][k]
    __shared__ float Bs[32 * 65];    // [k][col], pad 65 for conflict-free access

    const int tid = threadIdx.x;
    const int tx = tid & 15;         // 16 col groups * 4 cols
    const int ty = tid >> 4;         // 16 row groups * 8 rows
    const int r0 = blockIdx.x * 128;
    const int by = blockIdx.y;
    const int wsel = by >> 2;
    const float* wp = (wsel == 0) ? W : (wsel == 1) ? W1 : W2;
    float* outp     = (wsel == 0) ? g_val : (wsel == 1) ? g_hsrc : g_hdst;
    const int c0 = (by & 3) * 64;

    unsigned long long acc[4][4];
#pragma unroll
    for (int p = 0; p < 4; p++)
#pragma unroll
        for (int j = 0; j < 4; j++) acc[p][j] = 0ull;

    for (int kt = 0; kt < 4; kt++) {
        // load A tile: 128 rows x 32 k (1024 float4, 4 per thread), coalesced
#pragma unroll
        for (int jj = 0; jj < 4; jj++) {
            int f = tid + jj * 256;      // 0..1023
            int row = f >> 3;
            int k4 = f & 7;
            float4 v = make_float4(0.f, 0.f, 0.f, 0.f);
            int rg = r0 + row;
            if (rg < NN) v = *(const float4*)(x + rg * 128 + kt * 32 + k4 * 4);
            *(float4*)(As + row * 32 + k4 * 4) = v;
        }
        // load B tile transposed: 64 cols x 32 k (512 float4, 2 per thread)
#pragma unroll
        for (int jj = 0; jj < 2; jj++) {
            int f = tid + jj * 256;      // 0..511
            int c = f >> 3;
            int k4 = f & 7;
            float4 v = *(const float4*)(wp + (c0 + c) * 128 + kt * 32 + k4 * 4);
            Bs[(k4 * 4 + 0) * 65 + c] = v.x;
            Bs[(k4 * 4 + 1) * 65 + c] = v.y;
            Bs[(k4 * 4 + 2) * 65 + c] = v.z;
            Bs[(k4 * 4 + 3) * 65 + c] = v.w;
        }
        __syncthreads();

#pragma unroll
        for (int kk = 0; kk < 32; kk++) {
            float a[8];
#pragma unroll
            for (int i = 0; i < 8; i++) a[i] = As[(ty * 8 + i) * 32 + kk];  // broadcast
            unsigned long long ap[4];
#pragma unroll
            for (int p = 0; p < 4; p++) ap[p] = pk2(a[2 * p], a[2 * p + 1]);
            unsigned long long bp[4];
#pragma unroll
            for (int j = 0; j < 4; j++) {
                float b = Bs[kk * 65 + tx * 4 + j];                          // conflict-free
                bp[j] = pk2(b, b);
            }
#pragma unroll
            for (int p = 0; p < 4; p++)
#pragma unroll
                for (int j = 0; j < 4; j++) fma2(acc[p][j], ap[p], bp[j]);
        }
        __syncthreads();
    }

    // epilogue
#pragma unroll
    for (int p = 0; p < 4; p++) {
        int rg0 = r0 + ty * 8 + 2 * p;
#pragma unroll
        for (int j = 0; j < 4; j++) {
            int cg = c0 + tx * 4 + j;
            if (rg0 < NN)     outp[rg0 * HF + cg]       = lo32(acc[p][j]);
            if (rg0 + 1 < NN) outp[(rg0 + 1) * HF + cg] = hi32(acc[p][j]);
        }
    }
}

// ---------------- CSR build (dst-sorted src lists) ----------------
__global__ void zero_deg_kernel() {
    int i = blockIdx.x * 256 + threadIdx.x;
    if (i < NN) g_deg[i] = 0;
}
__global__ void hist_kernel(const int* __restrict__ ei) {
    int e = blockIdx.x * 256 + threadIdx.x;
    if (e < EE) atomicAdd(&g_deg[ei[EE + e]], 1);
}
__global__ void scan1_kernel() {
    __shared__ int s[1024];
    int t = threadIdx.x, b = blockIdx.x, i = b * 1024 + t;
    int v = (i < NN) ? g_deg[i] : 0;
    s[t] = v;
    __syncthreads();
    for (int off = 1; off < 1024; off <<= 1) {
        int x = 0;
        if (t >= off) x = s[t - off];
        __syncthreads();
        s[t] += x;
        __syncthreads();
    }
    if (i < NN) g_rowptr[i] = s[t] - v;   // block-local exclusive
    if (t == 1023) g_bsum[b] = s[t];
}
__global__ void scan2_kernel() {
    if (threadIdx.x == 0) {
        int run = 0;
        for (int b = 0; b < 20; b++) { g_boff[b] = run; run += g_bsum[b]; }
    }
}
__global__ void scan3_kernel() {
    int t = threadIdx.x, b = blockIdx.x, i = b * 1024 + t;
    if (i < NN) {
        int r = g_rowptr[i] + g_boff[b];
        g_rowptr[i] = r;
        g_cursor[i] = r;
    }
    if (i == 0) g_rowptr[NN] = EE;
}
__global__ void fill_kernel(const int* __restrict__ ei) {
    int e = blockIdx.x * 256 + threadIdx.x;
    if (e < EE) {
        int d = ei[EE + e];
        int p = atomicAdd(&g_cursor[d], 1);
        g_srcs[p] = ei[e];
    }
}

// ---------------- fused edge logits + softmax + aggregation ----------------
// One warp per dst node. Lane l owns features [l*8, l*8+8) -> head l/4.
__global__ __launch_bounds__(256) void gat_aggregate_kernel(
    const float* __restrict__ att, const float* __restrict__ bias,
    float* __restrict__ out)
{
    const int warp = threadIdx.x >> 5;
    const int lane = threadIdx.x & 31;
    const int n = blockIdx.x * 8 + warp;          // 2500*8 == 20000 exactly
    const int base = lane * 8;                    // flat [h*32+f] == lane*8 layout

    float4 a0 = *(const float4*)(att + base);
    float4 a1 = *(const float4*)(att + base + 4);
    const float* hd = g_hdst + (size_t)n * HF + base;
    float4 d0 = *(const float4*)(hd);
    float4 d1 = *(const float4*)(hd + 4);

    float acc[8] = {0.f, 0.f, 0.f, 0.f, 0.f, 0.f, 0.f, 0.f};
    float wsum = 0.f;

    const int js = g_rowptr[n];
    const int je = g_rowptr[n + 1];

    for (int j = js; j < je; j++) {
        int s = g_srcs[j];
        const float* hs = g_hsrc + (size_t)s * HF + base;
        const float* vv = g_val  + (size_t)s * HF + base;
        float4 s0 = *(const float4*)(hs);
        float4 s1 = *(const float4*)(hs + 4);
        float4 v0 = *(const float4*)(vv);
        float4 v1 = *(const float4*)(vv + 4);

        float p = 0.f, t;
        t = s0.x + d0.x; t = fmaxf(t, NEG * t); p += t * a0.x;
        t = s0.y + d0.y; t = fmaxf(t, NEG * t); p += t * a0.y;
        t = s0.z + d0.z; t = fmaxf(t, NEG * t); p += t * a0.z;
        t = s0.w + d0.w; t = fmaxf(t, NEG * t); p += t * a0.w;
        t = s1.x + d1.x; t = fmaxf(t, NEG * t); p += t * a1.x;
        t = s1.y + d1.y; t = fmaxf(t, NEG * t); p += t * a1.y;
        t = s1.z + d1.z; t = fmaxf(t, NEG * t); p += t * a1.z;
        t = s1.w + d1.w; t = fmaxf(t, NEG * t); p += t * a1.w;

        // reduce over the 4 lanes of this head
        p += __shfl_xor_sync(0xffffffffu, p, 1);
        p += __shfl_xor_sync(0xffffffffu, p, 2);

        float w = __expf(p);   // no max-subtraction: |logit| << 88, ratio identical
        wsum += w;

        acc[0] += w * v0.x; acc[1] += w * v0.y;
        acc[2] += w * v0.z; acc[3] += w * v0.w;
        acc[4] += w * v1.x; acc[5] += w * v1.y;
        acc[6] += w * v1.z; acc[7] += w * v1.w;
    }

    float inv = (wsum > 0.f) ? (1.0f / wsum) : 0.f;
    float4 b0 = *(const float4*)(bias + base);
    float4 b1 = *(const float4*)(bias + base + 4);
    float4 o0 = make_float4(acc[0] * inv + b0.x, acc[1] * inv + b0.y,
                            acc[2] * inv + b0.z, acc[3] * inv + b0.w);
    float4 o1 = make_float4(acc[4] * inv + b1.x, acc[5] * inv + b1.y,
                            acc[6] * inv + b1.z, acc[7] * inv + b1.w);
    float* op = out + (size_t)n * HF + base;
    *(float4*)(op)     = o0;
    *(float4*)(op + 4) = o1;
}

// ---------------- launch ----------------
extern "C" void kernel_launch(void* const* d_in, const int* in_sizes, int n_in,
                              void* d_out, int out_size) {
    const float* x    = (const float*)d_in[0];
    const int*   ei   = (const int*)d_in[1];
    const float* W    = (const float*)d_in[2];
    const float* W1   = (const float*)d_in[3];
    const float* W2   = (const float*)d_in[4];
    const float* att  = (const float*)d_in[5];
    const float* bias = (const float*)d_in[6];
    float* out = (float*)d_out;

    gemm_kernel<<<dim3(157, 12), 256>>>(x, W, W1, W2);
    zero_deg_kernel<<<(NN + 255) / 256, 256>>>();
    hist_kernel<<<(EE + 255) / 256, 256>>>(ei);
    scan1_kernel<<<20, 1024>>>();
    scan2_kernel<<<1, 32>>>();
    scan3_kernel<<<20, 1024>>>();
    fill_kernel<<<(EE + 255) / 256, 256>>>(ei);
    gat_aggregate_kernel<<<2500, 256>>>(att, bias, out);
}